// round 4
// baseline (speedup 1.0000x reference)
#include <cuda_runtime.h>
#include <cstdint>

// KVQuantizer: feat [1, 32, 8192, 128] f32 -> same shape.
// Per chunk of 16 tokens (per head): row0 -> 8-bit asym quant (base);
// rows 1..15: diff = x - base_deq, 4-bit asym quant, zero the 64
// smallest-|deq| per 128-group with lowest-index tie-break, out = base + pruned.
//
// Bit-match XLA:GPU semantics: f32 divide -> div.full.f32 (not div.rn),
// deq = fma(q, s, mn), round = rint (half-even).

#define WFULL 0xFFFFFFFFu

__device__ __forceinline__ float div_full(float a, float b) {
    float r;
    asm("div.full.f32 %0, %1, %2;" : "=f"(r) : "f"(a), "f"(b));
    return r;
}

__device__ __forceinline__ float quant_deq(float x, float mn, float s, float qmax, float& qf) {
    float t = div_full(__fsub_rn(x, mn), s);
    qf = fminf(fmaxf(rintf(t), 0.0f), qmax);
    return __fmaf_rn(qf, s, mn);
}

__global__ __launch_bounds__(512)
void kvq_kernel(const float* __restrict__ in, float* __restrict__ out) {
    const int S = 8192, D = 128;
    int blk  = blockIdx.x;        // h * 512 + chunk
    int h    = blk >> 9;
    int c    = blk & 511;
    int warp = threadIdx.x >> 5;
    int lane = threadIdx.x & 31;
    __shared__ float sbase[128];

    size_t chunkBase = ((size_t)h * S + ((size_t)c << 4)) * D;

    // ---- Phase 1: warp 0 computes the 8-bit base row ----
    if (warp == 0) {
        float4 v = *reinterpret_cast<const float4*>(in + chunkBase + lane * 4);
        float mn = fminf(fminf(v.x, v.y), fminf(v.z, v.w));
        float mx = fmaxf(fmaxf(v.x, v.y), fmaxf(v.z, v.w));
        #pragma unroll
        for (int o = 16; o > 0; o >>= 1) {
            mn = fminf(mn, __shfl_xor_sync(WFULL, mn, o));
            mx = fmaxf(mx, __shfl_xor_sync(WFULL, mx, o));
        }
        float s = fmaxf(div_full(__fsub_rn(mx, mn), 255.0f), 1e-5f);
        float qf;
        float4 b;
        b.x = quant_deq(v.x, mn, s, 255.0f, qf);
        b.y = quant_deq(v.y, mn, s, 255.0f, qf);
        b.z = quant_deq(v.z, mn, s, 255.0f, qf);
        b.w = quant_deq(v.w, mn, s, 255.0f, qf);
        *reinterpret_cast<float4*>(sbase + lane * 4) = b;
        // Row 0 output is exactly base_deq (zero diff quantizes to exactly 0).
        *reinterpret_cast<float4*>(out + chunkBase + lane * 4) = b;
    }
    __syncthreads();
    if (warp == 0) return;

    // ---- Phase 2: warp w handles diff row r = w (1..15) ----
    size_t rowOff = chunkBase + (size_t)warp * D;
    float4 v = *reinterpret_cast<const float4*>(in + rowOff + lane * 4);
    float4 b = *reinterpret_cast<const float4*>(sbase + lane * 4);

    float d0 = __fsub_rn(v.x, b.x);
    float d1 = __fsub_rn(v.y, b.y);
    float d2 = __fsub_rn(v.z, b.z);
    float d3 = __fsub_rn(v.w, b.w);

    float mn = fminf(fminf(d0, d1), fminf(d2, d3));
    float mx = fmaxf(fmaxf(d0, d1), fmaxf(d2, d3));
    #pragma unroll
    for (int o = 16; o > 0; o >>= 1) {
        mn = fminf(mn, __shfl_xor_sync(WFULL, mn, o));
        mx = fmaxf(mx, __shfl_xor_sync(WFULL, mx, o));
    }
    float s = fmaxf(div_full(__fsub_rn(mx, mn), 15.0f), 1e-5f);

    float q0f, q1f, q2f, q3f;
    float e0 = quant_deq(d0, mn, s, 15.0f, q0f);
    float e1 = quant_deq(d1, mn, s, 15.0f, q1f);
    float e2 = quant_deq(d2, mn, s, 15.0f, q2f);
    float e3 = quant_deq(d3, mn, s, 15.0f, q3f);
    int q0 = (int)q0f, q1 = (int)q1f, q2 = (int)q2f, q3 = (int)q3f;

    // ---- Histogram of 16 quant levels: packed byte counters in 2x u64 ----
    unsigned long long acc0 = 0, acc1 = 0;
    {
        unsigned long long o0 = 1ULL << ((q0 >> 1) * 8); if (q0 & 1) acc1 += o0; else acc0 += o0;
        unsigned long long o1 = 1ULL << ((q1 >> 1) * 8); if (q1 & 1) acc1 += o1; else acc0 += o1;
        unsigned long long o2 = 1ULL << ((q2 >> 1) * 8); if (q2 & 1) acc1 += o2; else acc0 += o2;
        unsigned long long o3 = 1ULL << ((q3 >> 1) * 8); if (q3 & 1) acc1 += o3; else acc0 += o3;
    }
    #pragma unroll
    for (int o = 16; o > 0; o >>= 1) {
        acc0 += __shfl_xor_sync(WFULL, acc0, o);
        acc1 += __shfl_xor_sync(WFULL, acc1, o);
    }
    // Lane l holds count of level l (l < 16).
    int cnt = (int)((((lane & 1) ? acc1 : acc0) >> ((lane >> 1) * 8)) & 0xFFULL);

    // Lane l holds level l's dequant value; find the 64th-smallest |deq|.
    float dl  = __fmaf_rn((float)lane, s, mn);
    float alv = fabsf(dl);
    int C = 0, E = 0;              // #elems strictly below / equal to alv
    #pragma unroll
    for (int m = 0; m < 16; m++) {
        float am = fabsf(__shfl_sync(WFULL, dl, m));
        int   cm = __shfl_sync(WFULL, cnt, m);
        C += (am <  alv) ? cm : 0;
        E += (am == alv) ? cm : 0;
    }
    unsigned flagB = __ballot_sync(WFULL, (lane < 16) && (C < 64) && (C + E >= 64));
    int bl = __ffs(flagB) - 1;                         // boundary level lane
    float    t     = __shfl_sync(WFULL, alv, bl);      // threshold |deq|
    int      need  = 64 - __shfl_sync(WFULL, C, bl);   // #boundary elems to zero
    unsigned bmask = __ballot_sync(WFULL, alv == t) & 0xFFFFu; // levels at t
    unsigned fullm = __ballot_sync(WFULL, alv <  t) & 0xFFFFu; // fully-zeroed levels

    // Index-ordered prefix among boundary elements (elem index = 4*lane + k).
    int m0 = (bmask >> q0) & 1;
    int m1 = (bmask >> q1) & 1;
    int m2 = (bmask >> q2) & 1;
    int m3 = (bmask >> q3) & 1;
    unsigned B0 = __ballot_sync(WFULL, m0);
    unsigned B1 = __ballot_sync(WFULL, m1);
    unsigned B2 = __ballot_sync(WFULL, m2);
    unsigned B3 = __ballot_sync(WFULL, m3);
    unsigned below = (1u << lane) - 1u;
    int preL = __popc(B0 & below) + __popc(B1 & below)
             + __popc(B2 & below) + __popc(B3 & below);

    bool z0 = ((fullm >> q0) & 1) || (m0 && (preL                < need));
    bool z1 = ((fullm >> q1) & 1) || (m1 && (preL + m0           < need));
    bool z2 = ((fullm >> q2) & 1) || (m2 && (preL + m0 + m1      < need));
    bool z3 = ((fullm >> q3) & 1) || (m3 && (preL + m0 + m1 + m2 < need));

    float4 o4;
    o4.x = __fadd_rn(b.x, z0 ? 0.0f : e0);
    o4.y = __fadd_rn(b.y, z1 ? 0.0f : e1);
    o4.z = __fadd_rn(b.z, z2 ? 0.0f : e2);
    o4.w = __fadd_rn(b.w, z3 ? 0.0f : e3);
    *reinterpret_cast<float4*>(out + rowOff + lane * 4) = o4;
}

extern "C" void kernel_launch(void* const* d_in, const int* in_sizes, int n_in,
                              void* d_out, int out_size) {
    const float* feat = (const float*)d_in[0];
    float* out = (float*)d_out;
    // 32 heads * 512 chunks; 512 threads = 16 warps = 1 chunk (16 rows) per block.
    kvq_kernel<<<32 * 512, 512>>>(feat, out);
}

// round 6
// speedup vs baseline: 1.1427x; 1.1427x over previous
#include <cuda_runtime.h>
#include <cstdint>

// KVQuantizer: feat [1, 32, 8192, 128] f32 -> same shape.
// Per chunk of 16 tokens (per head): row0 -> 8-bit asym quant (base);
// rows 1..15: diff = x - base_deq, 4-bit asym quant, zero the 64
// smallest-|deq| per 128-group with lowest-index tie-break, out = base + pruned.
// Bit-matches XLA:GPU: f32 divide -> div.full.f32, deq = fma(q,s,mn), rint.
// R6: integer redux.sync via order-preserving float<->s32 key (f32 redux
// absent on sm_103); halved C/E threshold loop via mirrored lanes 16-31.

#define WFULL 0xFFFFFFFFu

__device__ __forceinline__ float div_full(float a, float b) {
    float r;
    asm("div.full.f32 %0, %1, %2;" : "=f"(r) : "f"(a), "f"(b));
    return r;
}
// Order-preserving involution between f32 (no NaN/-0) and signed int.
__device__ __forceinline__ int f2key(float x) {
    int u = __float_as_int(x);
    return u ^ ((u >> 31) & 0x7fffffff);
}
__device__ __forceinline__ float key2f(int k) {
    return __int_as_float(k ^ ((k >> 31) & 0x7fffffff));
}
__device__ __forceinline__ int redux_min_i(int v) {
    int r;
    asm("redux.sync.min.s32 %0, %1, 0xffffffff;" : "=r"(r) : "r"(v));
    return r;
}
__device__ __forceinline__ int redux_max_i(int v) {
    int r;
    asm("redux.sync.max.s32 %0, %1, 0xffffffff;" : "=r"(r) : "r"(v));
    return r;
}
__device__ __forceinline__ float warp_min_f(float x) { return key2f(redux_min_i(f2key(x))); }
__device__ __forceinline__ float warp_max_f(float x) { return key2f(redux_max_i(f2key(x))); }

__device__ __forceinline__ float quant_deq(float x, float mn, float s, float qmax, float& qf) {
    float t = div_full(__fsub_rn(x, mn), s);
    qf = fminf(fmaxf(rintf(t), 0.0f), qmax);
    return __fmaf_rn(qf, s, mn);
}

__global__ __launch_bounds__(512)
void kvq_kernel(const float* __restrict__ in, float* __restrict__ out) {
    const int S = 8192, D = 128;
    int blk  = blockIdx.x;        // h * 512 + chunk
    int h    = blk >> 9;
    int c    = blk & 511;
    int warp = threadIdx.x >> 5;
    int lane = threadIdx.x & 31;
    __shared__ float sbase[128];

    size_t chunkBase = ((size_t)h * S + ((size_t)c << 4)) * D;

    // ---- Phase 1: warp 0 computes the 8-bit base row ----
    if (warp == 0) {
        float4 v = *reinterpret_cast<const float4*>(in + chunkBase + lane * 4);
        float mn = warp_min_f(fminf(fminf(v.x, v.y), fminf(v.z, v.w)));
        float mx = warp_max_f(fmaxf(fmaxf(v.x, v.y), fmaxf(v.z, v.w)));
        float s = fmaxf(div_full(__fsub_rn(mx, mn), 255.0f), 1e-5f);
        float qf;
        float4 b;
        b.x = quant_deq(v.x, mn, s, 255.0f, qf);
        b.y = quant_deq(v.y, mn, s, 255.0f, qf);
        b.z = quant_deq(v.z, mn, s, 255.0f, qf);
        b.w = quant_deq(v.w, mn, s, 255.0f, qf);
        *reinterpret_cast<float4*>(sbase + lane * 4) = b;
        // Row 0 output is exactly base_deq (zero diff quantizes to exactly 0).
        *reinterpret_cast<float4*>(out + chunkBase + lane * 4) = b;
    }
    __syncthreads();
    if (warp == 0) return;

    // ---- Phase 2: warp w handles diff row r = w (1..15) ----
    size_t rowOff = chunkBase + (size_t)warp * D;
    float4 v = *reinterpret_cast<const float4*>(in + rowOff + lane * 4);
    float4 b = *reinterpret_cast<const float4*>(sbase + lane * 4);

    float d0 = __fsub_rn(v.x, b.x);
    float d1 = __fsub_rn(v.y, b.y);
    float d2 = __fsub_rn(v.z, b.z);
    float d3 = __fsub_rn(v.w, b.w);

    float mn = warp_min_f(fminf(fminf(d0, d1), fminf(d2, d3)));
    float mx = warp_max_f(fmaxf(fmaxf(d0, d1), fmaxf(d2, d3)));
    float s  = fmaxf(div_full(__fsub_rn(mx, mn), 15.0f), 1e-5f);

    float q0f, q1f, q2f, q3f;
    float e0 = quant_deq(d0, mn, s, 15.0f, q0f);
    float e1 = quant_deq(d1, mn, s, 15.0f, q1f);
    float e2 = quant_deq(d2, mn, s, 15.0f, q2f);
    float e3 = quant_deq(d3, mn, s, 15.0f, q3f);
    int q0 = (int)q0f, q1 = (int)q1f, q2 = (int)q2f, q3 = (int)q3f;

    // ---- Histogram of 16 quant levels: packed byte counters in 2x u64 ----
    unsigned long long acc0 = 0, acc1 = 0;
    {
        unsigned long long o0 = 1ULL << ((q0 >> 1) * 8); if (q0 & 1) acc1 += o0; else acc0 += o0;
        unsigned long long o1 = 1ULL << ((q1 >> 1) * 8); if (q1 & 1) acc1 += o1; else acc0 += o1;
        unsigned long long o2 = 1ULL << ((q2 >> 1) * 8); if (q2 & 1) acc1 += o2; else acc0 += o2;
        unsigned long long o3 = 1ULL << ((q3 >> 1) * 8); if (q3 & 1) acc1 += o3; else acc0 += o3;
    }
    #pragma unroll
    for (int o = 16; o > 0; o >>= 1) {
        acc0 += __shfl_xor_sync(WFULL, acc0, o);
        acc1 += __shfl_xor_sync(WFULL, acc1, o);
    }
    // Mirrored levels: lanes l and l+16 both own level (l & 15).
    int lvl = lane & 15;
    int cnt = (int)((((lvl & 1) ? acc1 : acc0) >> ((lvl >> 1) * 8)) & 0xFFULL);

    // Level dequant value + |.|; find the 64th-smallest |deq|.
    float dl  = __fmaf_rn((float)lvl, s, mn);
    float alv = fabsf(dl);
    // Halved scan: lanes<16 sum source levels [0,8), lanes>=16 sum [8,16).
    int C = 0, E = 0;
    int mbase = (lane & 16) >> 1;   // 0 or 8
    #pragma unroll
    for (int m = 0; m < 8; m++) {
        float am = __shfl_sync(WFULL, alv, mbase + m);
        int   cm = __shfl_sync(WFULL, cnt, mbase + m);
        C += (am <  alv) ? cm : 0;
        E += (am == alv) ? cm : 0;
    }
    C += __shfl_xor_sync(WFULL, C, 16);
    E += __shfl_xor_sync(WFULL, E, 16);

    unsigned flagB = __ballot_sync(WFULL, (lane < 16) && (C < 64) && (C + E >= 64));
    int bl = __ffs(flagB) - 1;                         // boundary level lane
    float    t     = __shfl_sync(WFULL, alv, bl);      // threshold |deq|
    int      need  = 64 - __shfl_sync(WFULL, C, bl);   // #boundary elems to zero
    unsigned bmask = __ballot_sync(WFULL, alv == t) & 0xFFFFu; // levels at t
    unsigned fullm = __ballot_sync(WFULL, alv <  t) & 0xFFFFu; // fully-zeroed levels

    // Index-ordered prefix among boundary elements (elem index = 4*lane + k).
    int m0 = (bmask >> q0) & 1;
    int m1 = (bmask >> q1) & 1;
    int m2 = (bmask >> q2) & 1;
    int m3 = (bmask >> q3) & 1;
    unsigned B0 = __ballot_sync(WFULL, m0);
    unsigned B1 = __ballot_sync(WFULL, m1);
    unsigned B2 = __ballot_sync(WFULL, m2);
    unsigned B3 = __ballot_sync(WFULL, m3);
    unsigned below = (1u << lane) - 1u;
    int preL = __popc(B0 & below) + __popc(B1 & below)
             + __popc(B2 & below) + __popc(B3 & below);

    bool z0 = ((fullm >> q0) & 1) || (m0 && (preL                < need));
    bool z1 = ((fullm >> q1) & 1) || (m1 && (preL + m0           < need));
    bool z2 = ((fullm >> q2) & 1) || (m2 && (preL + m0 + m1      < need));
    bool z3 = ((fullm >> q3) & 1) || (m3 && (preL + m0 + m1 + m2 < need));

    float4 o4;
    o4.x = __fadd_rn(b.x, z0 ? 0.0f : e0);
    o4.y = __fadd_rn(b.y, z1 ? 0.0f : e1);
    o4.z = __fadd_rn(b.z, z2 ? 0.0f : e2);
    o4.w = __fadd_rn(b.w, z3 ? 0.0f : e3);
    *reinterpret_cast<float4*>(out + rowOff + lane * 4) = o4;
}

extern "C" void kernel_launch(void* const* d_in, const int* in_sizes, int n_in,
                              void* d_out, int out_size) {
    const float* feat = (const float*)d_in[0];
    float* out = (float*)d_out;
    // 32 heads * 512 chunks; 512 threads = 16 warps = 1 chunk (16 rows) per block.
    kvq_kernel<<<32 * 512, 512>>>(feat, out);
}

// round 7
// speedup vs baseline: 1.1608x; 1.0159x over previous
#include <cuda_runtime.h>
#include <cstdint>

// KVQuantizer: feat [1, 32, 8192, 128] f32 -> same shape.
// Per chunk of 16 tokens (per head): row0 -> 8-bit asym quant (base);
// rows 1..15: diff = x - base_deq, 4-bit asym quant, zero the 64
// smallest-|deq| per 128-group with lowest-index tie-break, out = base + pruned.
// Bit-matches XLA:GPU: f32 divide -> div.full.f32, deq = fma(q,s,mn), rint.
// R7: histogram reduced with redux.sync.add.u32 (4x one-instr reductions,
// full histogram broadcast to every lane); C/E scan de-shuffled (local FMA
// recompute of level values + register byte-extract of counts).

#define WFULL 0xFFFFFFFFu

__device__ __forceinline__ float div_full(float a, float b) {
    float r;
    asm("div.full.f32 %0, %1, %2;" : "=f"(r) : "f"(a), "f"(b));
    return r;
}
// Order-preserving involution between f32 (no NaN/-0 here) and signed int.
__device__ __forceinline__ int f2key(float x) {
    int u = __float_as_int(x);
    return u ^ ((u >> 31) & 0x7fffffff);
}
__device__ __forceinline__ float key2f(int k) {
    return __int_as_float(k ^ ((k >> 31) & 0x7fffffff));
}
__device__ __forceinline__ int redux_min_i(int v) {
    int r; asm("redux.sync.min.s32 %0, %1, 0xffffffff;" : "=r"(r) : "r"(v)); return r;
}
__device__ __forceinline__ int redux_max_i(int v) {
    int r; asm("redux.sync.max.s32 %0, %1, 0xffffffff;" : "=r"(r) : "r"(v)); return r;
}
__device__ __forceinline__ unsigned redux_add_u(unsigned v) {
    unsigned r; asm("redux.sync.add.u32 %0, %1, 0xffffffff;" : "=r"(r) : "r"(v)); return r;
}
__device__ __forceinline__ float warp_min_f(float x) { return key2f(redux_min_i(f2key(x))); }
__device__ __forceinline__ float warp_max_f(float x) { return key2f(redux_max_i(f2key(x))); }

__device__ __forceinline__ float quant_deq(float x, float mn, float s, float qmax, float& qf) {
    float t = div_full(__fsub_rn(x, mn), s);
    qf = fminf(fmaxf(rintf(t), 0.0f), qmax);
    return __fmaf_rn(qf, s, mn);
}

__global__ __launch_bounds__(512)
void kvq_kernel(const float* __restrict__ in, float* __restrict__ out) {
    const int S = 8192, D = 128;
    int blk  = blockIdx.x;        // h * 512 + chunk
    int h    = blk >> 9;
    int c    = blk & 511;
    int warp = threadIdx.x >> 5;
    int lane = threadIdx.x & 31;
    __shared__ float sbase[128];

    size_t chunkBase = ((size_t)h * S + ((size_t)c << 4)) * D;

    // ---- Phase 1: warp 0 computes the 8-bit base row ----
    if (warp == 0) {
        float4 v = *reinterpret_cast<const float4*>(in + chunkBase + lane * 4);
        float mn = warp_min_f(fminf(fminf(v.x, v.y), fminf(v.z, v.w)));
        float mx = warp_max_f(fmaxf(fmaxf(v.x, v.y), fmaxf(v.z, v.w)));
        float s = fmaxf(div_full(__fsub_rn(mx, mn), 255.0f), 1e-5f);
        float qf;
        float4 b;
        b.x = quant_deq(v.x, mn, s, 255.0f, qf);
        b.y = quant_deq(v.y, mn, s, 255.0f, qf);
        b.z = quant_deq(v.z, mn, s, 255.0f, qf);
        b.w = quant_deq(v.w, mn, s, 255.0f, qf);
        *reinterpret_cast<float4*>(sbase + lane * 4) = b;
        // Row 0 output is exactly base_deq (zero diff quantizes to exactly 0).
        *reinterpret_cast<float4*>(out + chunkBase + lane * 4) = b;
    }
    __syncthreads();
    if (warp == 0) return;

    // ---- Phase 2: warp w handles diff row r = w (1..15) ----
    size_t rowOff = chunkBase + (size_t)warp * D;
    float4 v = *reinterpret_cast<const float4*>(in + rowOff + lane * 4);
    float4 b = *reinterpret_cast<const float4*>(sbase + lane * 4);

    float d0 = __fsub_rn(v.x, b.x);
    float d1 = __fsub_rn(v.y, b.y);
    float d2 = __fsub_rn(v.z, b.z);
    float d3 = __fsub_rn(v.w, b.w);

    float mn = warp_min_f(fminf(fminf(d0, d1), fminf(d2, d3)));
    float mx = warp_max_f(fmaxf(fmaxf(d0, d1), fmaxf(d2, d3)));
    float s  = fmaxf(div_full(__fsub_rn(mx, mn), 15.0f), 1e-5f);

    float q0f, q1f, q2f, q3f;
    float e0 = quant_deq(d0, mn, s, 15.0f, q0f);
    float e1 = quant_deq(d1, mn, s, 15.0f, q1f);
    float e2 = quant_deq(d2, mn, s, 15.0f, q2f);
    float e3 = quant_deq(d3, mn, s, 15.0f, q3f);
    int q0 = (int)q0f, q1 = (int)q1f, q2 = (int)q2f, q3 = (int)q3f;

    // ---- Histogram: local packed byte counters, one redux per u32 ----
    // acc0 bytes = levels 0,2,4,..,14 ; acc1 bytes = levels 1,3,..,15.
    unsigned long long acc0 = 0, acc1 = 0;
    {
        unsigned long long o0 = 1ULL << ((q0 >> 1) * 8); if (q0 & 1) acc1 += o0; else acc0 += o0;
        unsigned long long o1 = 1ULL << ((q1 >> 1) * 8); if (q1 & 1) acc1 += o1; else acc0 += o1;
        unsigned long long o2 = 1ULL << ((q2 >> 1) * 8); if (q2 & 1) acc1 += o2; else acc0 += o2;
        unsigned long long o3 = 1ULL << ((q3 >> 1) * 8); if (q3 & 1) acc1 += o3; else acc0 += o3;
    }
    // Per-level counts <= 128, so byte lanes can't carry across. Every lane
    // ends up holding the full 16-bin histogram.
    unsigned hE0 = redux_add_u((unsigned)acc0);          // levels 0,2,4,6
    unsigned hE1 = redux_add_u((unsigned)(acc0 >> 32));  // levels 8,10,12,14
    unsigned hO0 = redux_add_u((unsigned)acc1);          // levels 1,3,5,7
    unsigned hO1 = redux_add_u((unsigned)(acc1 >> 32));  // levels 9,11,13,15

    // Mirrored levels: lanes l and l+16 both own level (l & 15).
    int lvl = lane & 15;
    // Level dequant value + |.| (bit-identical FMA wherever computed).
    float dl  = __fmaf_rn((float)lvl, s, mn);
    float alv = fabsf(dl);

    // Halved scan, no shuffles: lanes<16 scan source levels [0,8),
    // lanes>=16 scan [8,16). Counts come from local registers; level values
    // recomputed locally on the fma pipe.
    int mbase   = (lane & 16) >> 1;          // 0 or 8
    unsigned rE = mbase ? hE1 : hE0;         // even levels mbase+{0,2,4,6}
    unsigned rO = mbase ? hO1 : hO0;         // odd  levels mbase+{1,3,5,7}
    float fbase = (float)mbase;
    int C = 0, E = 0;
    #pragma unroll
    for (int m = 0; m < 8; m++) {
        float am = fabsf(__fmaf_rn(__fadd_rn(fbase, (float)m), s, mn));
        unsigned rr = (m & 1) ? rO : rE;
        int cm = (int)((rr >> ((m >> 1) * 8)) & 0xFFu);
        C += (am <  alv) ? cm : 0;
        E += (am == alv) ? cm : 0;
    }
    C += __shfl_xor_sync(WFULL, C, 16);
    E += __shfl_xor_sync(WFULL, E, 16);

    unsigned flagB = __ballot_sync(WFULL, (lane < 16) && (C < 64) && (C + E >= 64));
    int bl = __ffs(flagB) - 1;                         // boundary level lane
    float    t     = __shfl_sync(WFULL, alv, bl);      // threshold |deq|
    int      need  = 64 - __shfl_sync(WFULL, C, bl);   // #boundary elems to zero
    unsigned bmask = __ballot_sync(WFULL, alv == t) & 0xFFFFu; // levels at t
    unsigned fullm = __ballot_sync(WFULL, alv <  t) & 0xFFFFu; // fully-zeroed levels

    // Index-ordered prefix among boundary elements (elem index = 4*lane + k).
    int m0 = (bmask >> q0) & 1;
    int m1 = (bmask >> q1) & 1;
    int m2 = (bmask >> q2) & 1;
    int m3 = (bmask >> q3) & 1;
    unsigned B0 = __ballot_sync(WFULL, m0);
    unsigned B1 = __ballot_sync(WFULL, m1);
    unsigned B2 = __ballot_sync(WFULL, m2);
    unsigned B3 = __ballot_sync(WFULL, m3);
    unsigned below = (1u << lane) - 1u;
    int preL = __popc(B0 & below) + __popc(B1 & below)
             + __popc(B2 & below) + __popc(B3 & below);

    bool z0 = ((fullm >> q0) & 1) || (m0 && (preL                < need));
    bool z1 = ((fullm >> q1) & 1) || (m1 && (preL + m0           < need));
    bool z2 = ((fullm >> q2) & 1) || (m2 && (preL + m0 + m1      < need));
    bool z3 = ((fullm >> q3) & 1) || (m3 && (preL + m0 + m1 + m2 < need));

    float4 o4;
    o4.x = __fadd_rn(b.x, z0 ? 0.0f : e0);
    o4.y = __fadd_rn(b.y, z1 ? 0.0f : e1);
    o4.z = __fadd_rn(b.z, z2 ? 0.0f : e2);
    o4.w = __fadd_rn(b.w, z3 ? 0.0f : e3);
    *reinterpret_cast<float4*>(out + rowOff + lane * 4) = o4;
}

extern "C" void kernel_launch(void* const* d_in, const int* in_sizes, int n_in,
                              void* d_out, int out_size) {
    const float* feat = (const float*)d_in[0];
    float* out = (float*)d_out;
    // 32 heads * 512 chunks; 512 threads = 16 warps = 1 chunk (16 rows) per block.
    kvq_kernel<<<32 * 512, 512>>>(feat, out);
}

// round 8
// speedup vs baseline: 1.4200x; 1.2232x over previous
#include <cuda_runtime.h>
#include <cstdint>

// KVQuantizer: feat [1, 32, 8192, 128] f32 -> same shape.
// Per chunk of 16 tokens (per head): row0 -> 8-bit asym quant (base);
// rows 1..15: diff = x - base_deq, 4-bit asym quant, zero the 64
// smallest-|deq| per 128-group with lowest-index tie-break, out = base + pruned.
// Bit-matches XLA:GPU: f32 divide -> div.full.f32, deq = fma(q,s,mn), rint.
// R8: unpredicated u64-nibble histogram; float-compare epilogue (|e|<t / ==t
// replaces bitmask extraction); packed C/C+E counters; 32-bit float4 indexing.

#define WFULL 0xFFFFFFFFu

__device__ __forceinline__ float div_full(float a, float b) {
    float r;
    asm("div.full.f32 %0, %1, %2;" : "=f"(r) : "f"(a), "f"(b));
    return r;
}
// Order-preserving involution between f32 (no NaN/-0 here) and signed int.
__device__ __forceinline__ int f2key(float x) {
    int u = __float_as_int(x);
    return u ^ ((u >> 31) & 0x7fffffff);
}
__device__ __forceinline__ float key2f(int k) {
    return __int_as_float(k ^ ((k >> 31) & 0x7fffffff));
}
__device__ __forceinline__ int redux_min_i(int v) {
    int r; asm("redux.sync.min.s32 %0, %1, 0xffffffff;" : "=r"(r) : "r"(v)); return r;
}
__device__ __forceinline__ int redux_max_i(int v) {
    int r; asm("redux.sync.max.s32 %0, %1, 0xffffffff;" : "=r"(r) : "r"(v)); return r;
}
__device__ __forceinline__ unsigned redux_add_u(unsigned v) {
    unsigned r; asm("redux.sync.add.u32 %0, %1, 0xffffffff;" : "=r"(r) : "r"(v)); return r;
}
__device__ __forceinline__ float warp_min_f(float x) { return key2f(redux_min_i(f2key(x))); }
__device__ __forceinline__ float warp_max_f(float x) { return key2f(redux_max_i(f2key(x))); }

__device__ __forceinline__ float quant_deq(float x, float mn, float s, float qmax, float& qf) {
    float t = div_full(__fsub_rn(x, mn), s);
    qf = fminf(fmaxf(rintf(t), 0.0f), qmax);
    return __fmaf_rn(qf, s, mn);
}

__global__ __launch_bounds__(512)
void kvq_kernel(const float* __restrict__ in, float* __restrict__ out) {
    int blk  = blockIdx.x;
    int warp = threadIdx.x >> 5;
    int lane = threadIdx.x & 31;
    __shared__ float sbase[128];

    // Chunk = blk: float4 indices [blk*512, blk*512+512); row r at +r*32.
    const float4* in4  = reinterpret_cast<const float4*>(in);
    float4*       out4 = reinterpret_cast<float4*>(out);
    unsigned base4 = ((unsigned)blk << 9) | (unsigned)lane;          // row 0
    unsigned idx4  = base4 | ((unsigned)warp << 5);                  // row = warp

    // ---- Phase 1: warp 0 computes the 8-bit base row ----
    if (warp == 0) {
        float4 v = in4[base4];
        float mn = warp_min_f(fminf(fminf(v.x, v.y), fminf(v.z, v.w)));
        float mx = warp_max_f(fmaxf(fmaxf(v.x, v.y), fmaxf(v.z, v.w)));
        float s = fmaxf(div_full(__fsub_rn(mx, mn), 255.0f), 1e-5f);
        float qf;
        float4 b;
        b.x = quant_deq(v.x, mn, s, 255.0f, qf);
        b.y = quant_deq(v.y, mn, s, 255.0f, qf);
        b.z = quant_deq(v.z, mn, s, 255.0f, qf);
        b.w = quant_deq(v.w, mn, s, 255.0f, qf);
        *reinterpret_cast<float4*>(sbase + lane * 4) = b;
        // Row 0 output is exactly base_deq (zero diff quantizes to exactly 0).
        out4[base4] = b;
    }
    __syncthreads();
    if (warp == 0) return;

    // ---- Phase 2: warp w handles diff row r = w (1..15) ----
    float4 v = in4[idx4];
    float4 b = *reinterpret_cast<const float4*>(sbase + lane * 4);

    float d0 = __fsub_rn(v.x, b.x);
    float d1 = __fsub_rn(v.y, b.y);
    float d2 = __fsub_rn(v.z, b.z);
    float d3 = __fsub_rn(v.w, b.w);

    float mn = warp_min_f(fminf(fminf(d0, d1), fminf(d2, d3)));
    float mx = warp_max_f(fmaxf(fmaxf(d0, d1), fmaxf(d2, d3)));
    float s  = fmaxf(div_full(__fsub_rn(mx, mn), 15.0f), 1e-5f);

    float q0f, q1f, q2f, q3f;
    float e0 = quant_deq(d0, mn, s, 15.0f, q0f);
    float e1 = quant_deq(d1, mn, s, 15.0f, q1f);
    float e2 = quant_deq(d2, mn, s, 15.0f, q2f);
    float e3 = quant_deq(d3, mn, s, 15.0f, q3f);
    int q0 = (int)q0f, q1 = (int)q1f, q2 = (int)q2f, q3 = (int)q3f;

    // ---- Histogram: one unpredicated u64 nibble accumulator per lane ----
    // (per-lane bin count <= 4 fits a nibble; post-redux byte sums <= 128)
    unsigned long long hh = (1ULL << (q0 << 2)) + (1ULL << (q1 << 2))
                          + (1ULL << (q2 << 2)) + (1ULL << (q3 << 2));
    unsigned lo = (unsigned)hh, hi = (unsigned)(hh >> 32);
    unsigned hE0 = redux_add_u( lo        & 0x0F0F0F0Fu);  // levels 0,2,4,6
    unsigned hO0 = redux_add_u((lo >> 4)  & 0x0F0F0F0Fu);  // levels 1,3,5,7
    unsigned hE1 = redux_add_u( hi        & 0x0F0F0F0Fu);  // levels 8,10,12,14
    unsigned hO1 = redux_add_u((hi >> 4)  & 0x0F0F0F0Fu);  // levels 9,11,13,15

    // Mirrored levels: lanes l and l+16 both own level (l & 15).
    int lvl = lane & 15;
    float dl  = __fmaf_rn((float)lvl, s, mn);
    float alv = fabsf(dl);

    // Halved scan, shuffle-free: lanes<16 scan source levels [0,8),
    // lanes>=16 scan [8,16). CE packs {C_lt | C_le<<16} (each <= 128).
    bool hiHalf = (lane & 16) != 0;
    unsigned rE = hiHalf ? hE1 : hE0;
    unsigned rO = hiHalf ? hO1 : hO0;
    float fbase = hiHalf ? 8.0f : 0.0f;
    int CE = 0;
    #pragma unroll
    for (int m = 0; m < 8; m++) {
        float am = fabsf(__fmaf_rn(__fadd_rn(fbase, (float)m), s, mn));
        unsigned rr = (m & 1) ? rO : rE;
        int cm = __byte_perm(rr, 0u, 0x4440 | (m >> 1));   // zero-extended byte
        if (am <  alv) CE += cm;
        if (am <= alv) CE += (cm << 16);
    }
    CE += __shfl_xor_sync(WFULL, CE, 16);
    int Clt = CE & 0xFFFF;
    int Cle = (int)((unsigned)CE >> 16);

    // Boundary level: Clt < 64 <= Cle.
    unsigned flagB = __ballot_sync(WFULL, (lane < 16) && (Clt < 64) && (Cle >= 64));
    int bl = __ffs((int)flagB) - 1;
    float t   = __shfl_sync(WFULL, alv, bl);            // threshold |deq|
    int   CEb = __shfl_sync(WFULL, CE, bl);
    int  need = 64 - (CEb & 0xFFFF);                    // boundary elems to zero

    // Per-element: |e_k| is bit-identical to its level's alv (same FMA).
    // zero iff |e|<t, or |e|==t and index-ordered tie prefix < need.
    int eq0 = (fabsf(e0) == t);
    int eq1 = (fabsf(e1) == t);
    int eq2 = (fabsf(e2) == t);
    int eq3 = (fabsf(e3) == t);
    unsigned B0 = __ballot_sync(WFULL, eq0);
    unsigned B1 = __ballot_sync(WFULL, eq1);
    unsigned B2 = __ballot_sync(WFULL, eq2);
    unsigned B3 = __ballot_sync(WFULL, eq3);
    unsigned below = (1u << lane) - 1u;
    int pre = __popc(B0 & below) + __popc(B1 & below)
            + __popc(B2 & below) + __popc(B3 & below);

    bool z0 = (fabsf(e0) < t) || (eq0 && (pre                   < need));
    bool z1 = (fabsf(e1) < t) || (eq1 && (pre + eq0             < need));
    bool z2 = (fabsf(e2) < t) || (eq2 && (pre + eq0 + eq1       < need));
    bool z3 = (fabsf(e3) < t) || (eq3 && (pre + eq0 + eq1 + eq2 < need));

    float4 o4;
    o4.x = __fadd_rn(b.x, z0 ? 0.0f : e0);
    o4.y = __fadd_rn(b.y, z1 ? 0.0f : e1);
    o4.z = __fadd_rn(b.z, z2 ? 0.0f : e2);
    o4.w = __fadd_rn(b.w, z3 ? 0.0f : e3);
    out4[idx4] = o4;
}

extern "C" void kernel_launch(void* const* d_in, const int* in_sizes, int n_in,
                              void* d_out, int out_size) {
    const float* feat = (const float*)d_in[0];
    float* out = (float*)d_out;
    // 32 heads * 512 chunks; 512 threads = 16 warps = 1 chunk (16 rows) per block.
    kvq_kernel<<<32 * 512, 512>>>(feat, out);
}

// round 9
// speedup vs baseline: 1.4486x; 1.0202x over previous
#include <cuda_runtime.h>
#include <cstdint>

// KVQuantizer: feat [1, 32, 8192, 128] f32 -> same shape.
// Per chunk of 16 tokens (per head): row0 -> 8-bit asym quant (base);
// rows 1..15: diff = x - base_deq, 4-bit asym quant, zero the 64
// smallest-|deq| per 128-group with lowest-index tie-break, out = base + pruned.
// Bit-matches XLA:GPU: f32 divide -> div.full.f32, deq = fma(q,s,mn), rint.
// R9: Cle-only threshold scan (t = min alv with Cle>=64 via redux.min on raw
// bits; Cle_b via redux.max broadcast; need = 64 - Cle_b + E with E from the
// tie ballots) -- removes the packed C_lt accumulation and ffs/shfl chain.

#define WFULL 0xFFFFFFFFu

__device__ __forceinline__ float div_full(float a, float b) {
    float r;
    asm("div.full.f32 %0, %1, %2;" : "=f"(r) : "f"(a), "f"(b));
    return r;
}
// Order-preserving involution between f32 (no NaN/-0 here) and signed int.
__device__ __forceinline__ int f2key(float x) {
    int u = __float_as_int(x);
    return u ^ ((u >> 31) & 0x7fffffff);
}
__device__ __forceinline__ float key2f(int k) {
    return __int_as_float(k ^ ((k >> 31) & 0x7fffffff));
}
__device__ __forceinline__ int redux_min_i(int v) {
    int r; asm("redux.sync.min.s32 %0, %1, 0xffffffff;" : "=r"(r) : "r"(v)); return r;
}
__device__ __forceinline__ int redux_max_i(int v) {
    int r; asm("redux.sync.max.s32 %0, %1, 0xffffffff;" : "=r"(r) : "r"(v)); return r;
}
__device__ __forceinline__ unsigned redux_add_u(unsigned v) {
    unsigned r; asm("redux.sync.add.u32 %0, %1, 0xffffffff;" : "=r"(r) : "r"(v)); return r;
}
__device__ __forceinline__ float warp_min_f(float x) { return key2f(redux_min_i(f2key(x))); }
__device__ __forceinline__ float warp_max_f(float x) { return key2f(redux_max_i(f2key(x))); }

__device__ __forceinline__ float quant_deq(float x, float mn, float s, float qmax, float& qf) {
    float t = div_full(__fsub_rn(x, mn), s);
    qf = fminf(fmaxf(rintf(t), 0.0f), qmax);
    return __fmaf_rn(qf, s, mn);
}

__global__ __launch_bounds__(512)
void kvq_kernel(const float* __restrict__ in, float* __restrict__ out) {
    int blk  = blockIdx.x;
    int warp = threadIdx.x >> 5;
    int lane = threadIdx.x & 31;
    __shared__ float sbase[128];

    // Chunk = blk: float4 indices [blk*512, blk*512+512); row r at +r*32.
    const float4* in4  = reinterpret_cast<const float4*>(in);
    float4*       out4 = reinterpret_cast<float4*>(out);
    unsigned base4 = ((unsigned)blk << 9) | (unsigned)lane;          // row 0
    unsigned idx4  = base4 | ((unsigned)warp << 5);                  // row = warp

    // ---- Phase 1: warp 0 computes the 8-bit base row ----
    if (warp == 0) {
        float4 v = in4[base4];
        float mn = warp_min_f(fminf(fminf(v.x, v.y), fminf(v.z, v.w)));
        float mx = warp_max_f(fmaxf(fmaxf(v.x, v.y), fmaxf(v.z, v.w)));
        float s = fmaxf(div_full(__fsub_rn(mx, mn), 255.0f), 1e-5f);
        float qf;
        float4 b;
        b.x = quant_deq(v.x, mn, s, 255.0f, qf);
        b.y = quant_deq(v.y, mn, s, 255.0f, qf);
        b.z = quant_deq(v.z, mn, s, 255.0f, qf);
        b.w = quant_deq(v.w, mn, s, 255.0f, qf);
        *reinterpret_cast<float4*>(sbase + lane * 4) = b;
        // Row 0 output is exactly base_deq (zero diff quantizes to exactly 0).
        out4[base4] = b;
    }
    __syncthreads();
    if (warp == 0) return;

    // ---- Phase 2: warp w handles diff row r = w (1..15) ----
    float4 v = in4[idx4];
    float4 b = *reinterpret_cast<const float4*>(sbase + lane * 4);

    float d0 = __fsub_rn(v.x, b.x);
    float d1 = __fsub_rn(v.y, b.y);
    float d2 = __fsub_rn(v.z, b.z);
    float d3 = __fsub_rn(v.w, b.w);

    float mn = warp_min_f(fminf(fminf(d0, d1), fminf(d2, d3)));
    float mx = warp_max_f(fmaxf(fmaxf(d0, d1), fmaxf(d2, d3)));
    float s  = fmaxf(div_full(__fsub_rn(mx, mn), 15.0f), 1e-5f);

    float q0f, q1f, q2f, q3f;
    float e0 = quant_deq(d0, mn, s, 15.0f, q0f);
    float e1 = quant_deq(d1, mn, s, 15.0f, q1f);
    float e2 = quant_deq(d2, mn, s, 15.0f, q2f);
    float e3 = quant_deq(d3, mn, s, 15.0f, q3f);
    int q0 = (int)q0f, q1 = (int)q1f, q2 = (int)q2f, q3 = (int)q3f;

    // ---- Histogram: one unpredicated u64 nibble accumulator per lane ----
    // (per-lane bin count <= 4 fits a nibble; post-redux byte sums <= 128)
    unsigned long long hh = (1ULL << (q0 << 2)) + (1ULL << (q1 << 2))
                          + (1ULL << (q2 << 2)) + (1ULL << (q3 << 2));
    unsigned lo = (unsigned)hh, hi = (unsigned)(hh >> 32);
    unsigned hE0 = redux_add_u( lo        & 0x0F0F0F0Fu);  // levels 0,2,4,6
    unsigned hO0 = redux_add_u((lo >> 4)  & 0x0F0F0F0Fu);  // levels 1,3,5,7
    unsigned hE1 = redux_add_u( hi        & 0x0F0F0F0Fu);  // levels 8,10,12,14
    unsigned hO1 = redux_add_u((hi >> 4)  & 0x0F0F0F0Fu);  // levels 9,11,13,15

    // Mirrored levels: lanes l and l+16 both own level (l & 15).
    int lvl = lane & 15;
    float dl  = __fmaf_rn((float)lvl, s, mn);
    float alv = fabsf(dl);

    // Halved scan, shuffle-free, Cle only (count of elements with |deq|<=alv):
    // lanes<16 scan source levels [0,8), lanes>=16 scan [8,16).
    bool hiHalf = (lane & 16) != 0;
    unsigned rE = hiHalf ? hE1 : hE0;
    unsigned rO = hiHalf ? hO1 : hO0;
    float fbase = hiHalf ? 8.0f : 0.0f;
    int CE = 0;
    #pragma unroll
    for (int m = 0; m < 8; m++) {
        float am = fabsf(__fmaf_rn(__fadd_rn(fbase, (float)m), s, mn));
        unsigned rr = (m & 1) ? rO : rE;
        int cm = __byte_perm(rr, 0u, 0x4440 | (m >> 1));   // zero-extended byte
        if (am <= alv) CE += cm;
    }
    CE += __shfl_xor_sync(WFULL, CE, 16);   // lanes l, l+16 now both hold Cle(l&15)

    // Boundary: t = min alv among levels with Cle >= 64 (always nonempty:
    // the max-alv level has Cle = 128). alv >= 0 so bits are order-isomorphic.
    int key = (CE >= 64) ? __float_as_int(alv) : 0x7fffffff;
    float t = __int_as_float(redux_min_i(key));
    // Cle at the boundary (all levels with alv == t share the same Cle >= 64).
    int Cb = redux_max_i((alv == t) ? CE : 0);

    // Per-element: |e_k| is bit-identical to its level's alv (same FMA).
    int eq0 = (fabsf(e0) == t);
    int eq1 = (fabsf(e1) == t);
    int eq2 = (fabsf(e2) == t);
    int eq3 = (fabsf(e3) == t);
    unsigned B0 = __ballot_sync(WFULL, eq0);
    unsigned B1 = __ballot_sync(WFULL, eq1);
    unsigned B2 = __ballot_sync(WFULL, eq2);
    unsigned B3 = __ballot_sync(WFULL, eq3);
    unsigned below = (1u << lane) - 1u;
    int pre = __popc(B0 & below) + __popc(B1 & below)
            + __popc(B2 & below) + __popc(B3 & below);

    // E = total elements equal to t; need = 64 - Clt(b) = 64 - (Cb - E).
    int E = (int)redux_add_u((unsigned)(eq0 + eq1 + eq2 + eq3));
    int need = 64 - Cb + E;

    bool z0 = (fabsf(e0) < t) || (eq0 && (pre                   < need));
    bool z1 = (fabsf(e1) < t) || (eq1 && (pre + eq0             < need));
    bool z2 = (fabsf(e2) < t) || (eq2 && (pre + eq0 + eq1       < need));
    bool z3 = (fabsf(e3) < t) || (eq3 && (pre + eq0 + eq1 + eq2 < need));

    float4 o4;
    o4.x = __fadd_rn(b.x, z0 ? 0.0f : e0);
    o4.y = __fadd_rn(b.y, z1 ? 0.0f : e1);
    o4.z = __fadd_rn(b.z, z2 ? 0.0f : e2);
    o4.w = __fadd_rn(b.w, z3 ? 0.0f : e3);
    out4[idx4] = o4;
}

extern "C" void kernel_launch(void* const* d_in, const int* in_sizes, int n_in,
                              void* d_out, int out_size) {
    const float* feat = (const float*)d_in[0];
    float* out = (float*)d_out;
    // 32 heads * 512 chunks; 512 threads = 16 warps = 1 chunk (16 rows) per block.
    kvq_kernel<<<32 * 512, 512>>>(feat, out);
}

// round 10
// speedup vs baseline: 1.7313x; 1.1951x over previous
#include <cuda_runtime.h>
#include <cstdint>

// KVQuantizer: feat [1, 32, 8192, 128] f32 -> same shape.
// Per chunk of 16 tokens (per head): row0 -> 8-bit asym quant (base);
// rows 1..15: diff = x - base_deq, 4-bit asym quant, zero the 64
// smallest-|deq| per 128-group with lowest-index tie-break, out = base + pruned.
// Bit-matches XLA:GPU: f32 divide -> div.full.f32, deq = fma(q,s,mn), rint.
// R10: 2 chunks per block, 2 independent rows per warp interleaved for ILP
// (hides redux/shfl/ballot/MUFU latency); loads hoisted above __syncthreads.

#define WFULL 0xFFFFFFFFu

__device__ __forceinline__ float div_full(float a, float b) {
    float r;
    asm("div.full.f32 %0, %1, %2;" : "=f"(r) : "f"(a), "f"(b));
    return r;
}
// Order-preserving involution between f32 (no NaN/-0 here) and signed int.
__device__ __forceinline__ int f2key(float x) {
    int u = __float_as_int(x);
    return u ^ ((u >> 31) & 0x7fffffff);
}
__device__ __forceinline__ float key2f(int k) {
    return __int_as_float(k ^ ((k >> 31) & 0x7fffffff));
}
__device__ __forceinline__ int redux_min_i(int v) {
    int r; asm("redux.sync.min.s32 %0, %1, 0xffffffff;" : "=r"(r) : "r"(v)); return r;
}
__device__ __forceinline__ int redux_max_i(int v) {
    int r; asm("redux.sync.max.s32 %0, %1, 0xffffffff;" : "=r"(r) : "r"(v)); return r;
}
__device__ __forceinline__ unsigned redux_add_u(unsigned v) {
    unsigned r; asm("redux.sync.add.u32 %0, %1, 0xffffffff;" : "=r"(r) : "r"(v)); return r;
}
__device__ __forceinline__ float warp_min_f(float x) { return key2f(redux_min_i(f2key(x))); }
__device__ __forceinline__ float warp_max_f(float x) { return key2f(redux_max_i(f2key(x))); }

__device__ __forceinline__ float quant_deq(float x, float mn, float s, float qmax, float& qf) {
    float t = div_full(__fsub_rn(x, mn), s);
    qf = fminf(fmaxf(rintf(t), 0.0f), qmax);
    return __fmaf_rn(qf, s, mn);
}

__global__ __launch_bounds__(512)
void kvq_kernel(const float* __restrict__ in, float* __restrict__ out) {
    int blk  = blockIdx.x;                 // handles chunks 2*blk (A), 2*blk+1 (B)
    int warp = threadIdx.x >> 5;
    int lane = threadIdx.x & 31;
    __shared__ float sbase[256];           // [0:128) chunk A base, [128:256) chunk B

    const float4* in4  = reinterpret_cast<const float4*>(in);
    float4*       out4 = reinterpret_cast<float4*>(out);
    unsigned a0 = ((unsigned)blk << 10) | (unsigned)lane;   // chunk A row0
    unsigned b0 = a0 + 512u;                                // chunk B row0
    unsigned ia = a0 | ((unsigned)warp << 5);               // chunk A row=warp
    unsigned ib = b0 | ((unsigned)warp << 5);               // chunk B row=warp

    // Hoisted loads: all warps issue both global loads before any sync.
    float4 vA = in4[ia];
    float4 vB = in4[ib];

    // ---- Phase 1: warp 0 computes both 8-bit base rows (dual-interleaved) ----
    if (warp == 0) {
        float mnA = warp_min_f(fminf(fminf(vA.x, vA.y), fminf(vA.z, vA.w)));
        float mnB = warp_min_f(fminf(fminf(vB.x, vB.y), fminf(vB.z, vB.w)));
        float mxA = warp_max_f(fmaxf(fmaxf(vA.x, vA.y), fmaxf(vA.z, vA.w)));
        float mxB = warp_max_f(fmaxf(fmaxf(vB.x, vB.y), fmaxf(vB.z, vB.w)));
        float sA = fmaxf(div_full(__fsub_rn(mxA, mnA), 255.0f), 1e-5f);
        float sB = fmaxf(div_full(__fsub_rn(mxB, mnB), 255.0f), 1e-5f);
        float qf;
        float4 bA, bB;
        bA.x = quant_deq(vA.x, mnA, sA, 255.0f, qf);
        bB.x = quant_deq(vB.x, mnB, sB, 255.0f, qf);
        bA.y = quant_deq(vA.y, mnA, sA, 255.0f, qf);
        bB.y = quant_deq(vB.y, mnB, sB, 255.0f, qf);
        bA.z = quant_deq(vA.z, mnA, sA, 255.0f, qf);
        bB.z = quant_deq(vB.z, mnB, sB, 255.0f, qf);
        bA.w = quant_deq(vA.w, mnA, sA, 255.0f, qf);
        bB.w = quant_deq(vB.w, mnB, sB, 255.0f, qf);
        *reinterpret_cast<float4*>(sbase + lane * 4)       = bA;
        *reinterpret_cast<float4*>(sbase + 128 + lane * 4) = bB;
        // Row 0 output is exactly base_deq (zero diff quantizes to exactly 0).
        out4[a0] = bA;
        out4[b0] = bB;
    }
    __syncthreads();
    if (warp == 0) return;

    // ---- Phase 2: warp w handles diff row w of BOTH chunks, interleaved ----
    float4 bA = *reinterpret_cast<const float4*>(sbase + lane * 4);
    float4 bB = *reinterpret_cast<const float4*>(sbase + 128 + lane * 4);

    float dA0 = __fsub_rn(vA.x, bA.x), dB0 = __fsub_rn(vB.x, bB.x);
    float dA1 = __fsub_rn(vA.y, bA.y), dB1 = __fsub_rn(vB.y, bB.y);
    float dA2 = __fsub_rn(vA.z, bA.z), dB2 = __fsub_rn(vB.z, bB.z);
    float dA3 = __fsub_rn(vA.w, bA.w), dB3 = __fsub_rn(vB.w, bB.w);

    float mnA = warp_min_f(fminf(fminf(dA0, dA1), fminf(dA2, dA3)));
    float mnB = warp_min_f(fminf(fminf(dB0, dB1), fminf(dB2, dB3)));
    float mxA = warp_max_f(fmaxf(fmaxf(dA0, dA1), fmaxf(dA2, dA3)));
    float mxB = warp_max_f(fmaxf(fmaxf(dB0, dB1), fmaxf(dB2, dB3)));
    float sA  = fmaxf(div_full(__fsub_rn(mxA, mnA), 15.0f), 1e-5f);
    float sB  = fmaxf(div_full(__fsub_rn(mxB, mnB), 15.0f), 1e-5f);

    float qA0f, qA1f, qA2f, qA3f, qB0f, qB1f, qB2f, qB3f;
    float eA0 = quant_deq(dA0, mnA, sA, 15.0f, qA0f);
    float eB0 = quant_deq(dB0, mnB, sB, 15.0f, qB0f);
    float eA1 = quant_deq(dA1, mnA, sA, 15.0f, qA1f);
    float eB1 = quant_deq(dB1, mnB, sB, 15.0f, qB1f);
    float eA2 = quant_deq(dA2, mnA, sA, 15.0f, qA2f);
    float eB2 = quant_deq(dB2, mnB, sB, 15.0f, qB2f);
    float eA3 = quant_deq(dA3, mnA, sA, 15.0f, qA3f);
    float eB3 = quant_deq(dB3, mnB, sB, 15.0f, qB3f);
    int qA0 = (int)qA0f, qA1 = (int)qA1f, qA2 = (int)qA2f, qA3 = (int)qA3f;
    int qB0 = (int)qB0f, qB1 = (int)qB1f, qB2 = (int)qB2f, qB3 = (int)qB3f;

    // ---- Histograms: unpredicated u64 nibble accumulators ----
    unsigned long long hhA = (1ULL << (qA0 << 2)) + (1ULL << (qA1 << 2))
                           + (1ULL << (qA2 << 2)) + (1ULL << (qA3 << 2));
    unsigned long long hhB = (1ULL << (qB0 << 2)) + (1ULL << (qB1 << 2))
                           + (1ULL << (qB2 << 2)) + (1ULL << (qB3 << 2));
    unsigned loA = (unsigned)hhA, hiA = (unsigned)(hhA >> 32);
    unsigned loB = (unsigned)hhB, hiB = (unsigned)(hhB >> 32);
    unsigned hE0A = redux_add_u( loA       & 0x0F0F0F0Fu);
    unsigned hE0B = redux_add_u( loB       & 0x0F0F0F0Fu);
    unsigned hO0A = redux_add_u((loA >> 4) & 0x0F0F0F0Fu);
    unsigned hO0B = redux_add_u((loB >> 4) & 0x0F0F0F0Fu);
    unsigned hE1A = redux_add_u( hiA       & 0x0F0F0F0Fu);
    unsigned hE1B = redux_add_u( hiB       & 0x0F0F0F0Fu);
    unsigned hO1A = redux_add_u((hiA >> 4) & 0x0F0F0F0Fu);
    unsigned hO1B = redux_add_u((hiB >> 4) & 0x0F0F0F0Fu);

    // Mirrored levels: lanes l and l+16 both own level (l & 15).
    int lvl = lane & 15;
    float alvA = fabsf(__fmaf_rn((float)lvl, sA, mnA));
    float alvB = fabsf(__fmaf_rn((float)lvl, sB, mnB));

    // Halved Cle scan, shuffle-free: lanes<16 scan levels [0,8), lanes>=16 [8,16).
    bool hiHalf = (lane & 16) != 0;
    unsigned rEA = hiHalf ? hE1A : hE0A;
    unsigned rOA = hiHalf ? hO1A : hO0A;
    unsigned rEB = hiHalf ? hE1B : hE0B;
    unsigned rOB = hiHalf ? hO1B : hO0B;
    float fbase = hiHalf ? 8.0f : 0.0f;
    int CEA = 0, CEB = 0;
    #pragma unroll
    for (int m = 0; m < 8; m++) {
        float lm  = __fadd_rn(fbase, (float)m);
        float amA = fabsf(__fmaf_rn(lm, sA, mnA));
        float amB = fabsf(__fmaf_rn(lm, sB, mnB));
        unsigned rrA = (m & 1) ? rOA : rEA;
        unsigned rrB = (m & 1) ? rOB : rEB;
        int cmA = __byte_perm(rrA, 0u, 0x4440 | (m >> 1));
        int cmB = __byte_perm(rrB, 0u, 0x4440 | (m >> 1));
        if (amA <= alvA) CEA += cmA;
        if (amB <= alvB) CEB += cmB;
    }
    CEA += __shfl_xor_sync(WFULL, CEA, 16);
    CEB += __shfl_xor_sync(WFULL, CEB, 16);

    // t = min alv among levels with Cle >= 64 (alv >= 0: bits order-isomorphic).
    int keyA = (CEA >= 64) ? __float_as_int(alvA) : 0x7fffffff;
    int keyB = (CEB >= 64) ? __float_as_int(alvB) : 0x7fffffff;
    float tA = __int_as_float(redux_min_i(keyA));
    float tB = __int_as_float(redux_min_i(keyB));
    int CbA = redux_max_i((alvA == tA) ? CEA : 0);
    int CbB = redux_max_i((alvB == tB) ? CEB : 0);

    // Per-element: |e_k| is bit-identical to its level's alv (same FMA).
    int eqA0 = (fabsf(eA0) == tA), eqB0 = (fabsf(eB0) == tB);
    int eqA1 = (fabsf(eA1) == tA), eqB1 = (fabsf(eB1) == tB);
    int eqA2 = (fabsf(eA2) == tA), eqB2 = (fabsf(eB2) == tB);
    int eqA3 = (fabsf(eA3) == tA), eqB3 = (fabsf(eB3) == tB);
    unsigned BA0 = __ballot_sync(WFULL, eqA0), BB0 = __ballot_sync(WFULL, eqB0);
    unsigned BA1 = __ballot_sync(WFULL, eqA1), BB1 = __ballot_sync(WFULL, eqB1);
    unsigned BA2 = __ballot_sync(WFULL, eqA2), BB2 = __ballot_sync(WFULL, eqB2);
    unsigned BA3 = __ballot_sync(WFULL, eqA3), BB3 = __ballot_sync(WFULL, eqB3);
    unsigned below = (1u << lane) - 1u;
    int preA = __popc(BA0 & below) + __popc(BA1 & below)
             + __popc(BA2 & below) + __popc(BA3 & below);
    int preB = __popc(BB0 & below) + __popc(BB1 & below)
             + __popc(BB2 & below) + __popc(BB3 & below);

    int EA = (int)redux_add_u((unsigned)(eqA0 + eqA1 + eqA2 + eqA3));
    int EB = (int)redux_add_u((unsigned)(eqB0 + eqB1 + eqB2 + eqB3));
    int needA = 64 - CbA + EA;
    int needB = 64 - CbB + EB;

    bool zA0 = (fabsf(eA0) < tA) || (eqA0 && (preA                      < needA));
    bool zA1 = (fabsf(eA1) < tA) || (eqA1 && (preA + eqA0               < needA));
    bool zA2 = (fabsf(eA2) < tA) || (eqA2 && (preA + eqA0 + eqA1        < needA));
    bool zA3 = (fabsf(eA3) < tA) || (eqA3 && (preA + eqA0 + eqA1 + eqA2 < needA));
    bool zB0 = (fabsf(eB0) < tB) || (eqB0 && (preB                      < needB));
    bool zB1 = (fabsf(eB1) < tB) || (eqB1 && (preB + eqB0               < needB));
    bool zB2 = (fabsf(eB2) < tB) || (eqB2 && (preB + eqB0 + eqB1        < needB));
    bool zB3 = (fabsf(eB3) < tB) || (eqB3 && (preB + eqB0 + eqB1 + eqB2 < needB));

    float4 oA, oB;
    oA.x = __fadd_rn(bA.x, zA0 ? 0.0f : eA0);
    oA.y = __fadd_rn(bA.y, zA1 ? 0.0f : eA1);
    oA.z = __fadd_rn(bA.z, zA2 ? 0.0f : eA2);
    oA.w = __fadd_rn(bA.w, zA3 ? 0.0f : eA3);
    oB.x = __fadd_rn(bB.x, zB0 ? 0.0f : eB0);
    oB.y = __fadd_rn(bB.y, zB1 ? 0.0f : eB1);
    oB.z = __fadd_rn(bB.z, zB2 ? 0.0f : eB2);
    oB.w = __fadd_rn(bB.w, zB3 ? 0.0f : eB3);
    out4[ia] = oA;
    out4[ib] = oB;
}

extern "C" void kernel_launch(void* const* d_in, const int* in_sizes, int n_in,
                              void* d_out, int out_size) {
    const float* feat = (const float*)d_in[0];
    float* out = (float*)d_out;
    // 16384 chunks total; each 512-thread block handles 2 chunks
    // (warp w processes row w of both chunks, interleaved for ILP).
    kvq_kernel<<<16384 / 2, 512>>>(feat, out);
}

// round 11
// speedup vs baseline: 1.7819x; 1.0293x over previous
#include <cuda_runtime.h>
#include <cstdint>

// KVQuantizer: feat [1, 32, 8192, 128] f32 -> same shape.
// Per chunk of 16 tokens (per head): row0 -> 8-bit asym quant (base);
// rows 1..15: diff = x - base_deq, 4-bit asym quant, zero the 64
// smallest-|deq| per 128-group with lowest-index tie-break, out = base + pruned.
// Bit-matches XLA:GPU: f32 divide -> div.full.f32, deq = fma(q,s,mn), rint.
// R11: two barrier-free kernels. k1 writes all base rows into out (row 0 of
// each chunk IS base_deq). k2 reads bases back from out (8MB, L2-resident),
// processes 2 independent diff rows per warp -- no smem, no syncthreads,
// homogeneous warps, 256-thread blocks.

#define WFULL 0xFFFFFFFFu

__device__ __forceinline__ float div_full(float a, float b) {
    float r;
    asm("div.full.f32 %0, %1, %2;" : "=f"(r) : "f"(a), "f"(b));
    return r;
}
// Order-preserving involution between f32 (no NaN/-0 here) and signed int.
__device__ __forceinline__ int f2key(float x) {
    int u = __float_as_int(x);
    return u ^ ((u >> 31) & 0x7fffffff);
}
__device__ __forceinline__ float key2f(int k) {
    return __int_as_float(k ^ ((k >> 31) & 0x7fffffff));
}
__device__ __forceinline__ int redux_min_i(int v) {
    int r; asm("redux.sync.min.s32 %0, %1, 0xffffffff;" : "=r"(r) : "r"(v)); return r;
}
__device__ __forceinline__ int redux_max_i(int v) {
    int r; asm("redux.sync.max.s32 %0, %1, 0xffffffff;" : "=r"(r) : "r"(v)); return r;
}
__device__ __forceinline__ unsigned redux_add_u(unsigned v) {
    unsigned r; asm("redux.sync.add.u32 %0, %1, 0xffffffff;" : "=r"(r) : "r"(v)); return r;
}
__device__ __forceinline__ float warp_min_f(float x) { return key2f(redux_min_i(f2key(x))); }
__device__ __forceinline__ float warp_max_f(float x) { return key2f(redux_max_i(f2key(x))); }

__device__ __forceinline__ float quant_deq(float x, float mn, float s, float qmax, float& qf) {
    float t = div_full(__fsub_rn(x, mn), s);
    qf = fminf(fmaxf(rintf(t), 0.0f), qmax);
    return __fmaf_rn(qf, s, mn);
}

// ---- Kernel 1: all 16384 base rows. Warp handles 2 chunks (A, B) for ILP.
__global__ __launch_bounds__(256)
void kvq_base_kernel(const float* __restrict__ in, float* __restrict__ out) {
    int flat = (blockIdx.x << 3) + (threadIdx.x >> 5);   // warp id in [0, 8192)
    int lane = threadIdx.x & 31;
    const float4* in4  = reinterpret_cast<const float4*>(in);
    float4*       out4 = reinterpret_cast<float4*>(out);
    unsigned ia = ((unsigned)flat << 10) | (unsigned)lane;   // chunk 2*flat row0
    unsigned ib = ia + 512u;                                  // chunk 2*flat+1 row0

    float4 vA = in4[ia];
    float4 vB = in4[ib];

    float mnA = warp_min_f(fminf(fminf(vA.x, vA.y), fminf(vA.z, vA.w)));
    float mnB = warp_min_f(fminf(fminf(vB.x, vB.y), fminf(vB.z, vB.w)));
    float mxA = warp_max_f(fmaxf(fmaxf(vA.x, vA.y), fmaxf(vA.z, vA.w)));
    float mxB = warp_max_f(fmaxf(fmaxf(vB.x, vB.y), fmaxf(vB.z, vB.w)));
    float sA = fmaxf(div_full(__fsub_rn(mxA, mnA), 255.0f), 1e-5f);
    float sB = fmaxf(div_full(__fsub_rn(mxB, mnB), 255.0f), 1e-5f);
    float qf;
    float4 bA, bB;
    bA.x = quant_deq(vA.x, mnA, sA, 255.0f, qf);
    bB.x = quant_deq(vB.x, mnB, sB, 255.0f, qf);
    bA.y = quant_deq(vA.y, mnA, sA, 255.0f, qf);
    bB.y = quant_deq(vB.y, mnB, sB, 255.0f, qf);
    bA.z = quant_deq(vA.z, mnA, sA, 255.0f, qf);
    bB.z = quant_deq(vB.z, mnB, sB, 255.0f, qf);
    bA.w = quant_deq(vA.w, mnA, sA, 255.0f, qf);
    bB.w = quant_deq(vB.w, mnB, sB, 255.0f, qf);
    // Row 0 output is exactly base_deq (zero diff quantizes to exactly 0).
    out4[ia] = bA;
    out4[ib] = bB;
}

// ---- Kernel 2: 245760 diff rows. Warp handles row r of chunk pair (A, B),
// interleaved for ILP. Bases read back from out (row 0 slots, L2-resident).
__global__ __launch_bounds__(256)
void kvq_diff_kernel(const float* __restrict__ in, float* __restrict__ out) {
    int flat = (blockIdx.x << 3) + (threadIdx.x >> 5);   // [0, 122880)
    int lane = threadIdx.x & 31;
    int p = flat / 15;                  // chunk pair index [0, 8192)
    int r = flat - p * 15 + 1;          // row 1..15

    const float4* in4  = reinterpret_cast<const float4*>(in);
    float4*       out4 = reinterpret_cast<float4*>(out);
    unsigned a0 = ((unsigned)p << 10) | (unsigned)lane;   // chunk A row0
    unsigned b0 = a0 + 512u;                              // chunk B row0
    unsigned ia = a0 + ((unsigned)r << 5);
    unsigned ib = b0 + ((unsigned)r << 5);

    // Issue all 4 loads up front (bases come from out, written by kernel 1).
    float4 vA = in4[ia];
    float4 vB = in4[ib];
    float4 bA = out4[a0];
    float4 bB = out4[b0];

    float dA0 = __fsub_rn(vA.x, bA.x), dB0 = __fsub_rn(vB.x, bB.x);
    float dA1 = __fsub_rn(vA.y, bA.y), dB1 = __fsub_rn(vB.y, bB.y);
    float dA2 = __fsub_rn(vA.z, bA.z), dB2 = __fsub_rn(vB.z, bB.z);
    float dA3 = __fsub_rn(vA.w, bA.w), dB3 = __fsub_rn(vB.w, bB.w);

    float mnA = warp_min_f(fminf(fminf(dA0, dA1), fminf(dA2, dA3)));
    float mnB = warp_min_f(fminf(fminf(dB0, dB1), fminf(dB2, dB3)));
    float mxA = warp_max_f(fmaxf(fmaxf(dA0, dA1), fmaxf(dA2, dA3)));
    float mxB = warp_max_f(fmaxf(fmaxf(dB0, dB1), fmaxf(dB2, dB3)));
    float sA  = fmaxf(div_full(__fsub_rn(mxA, mnA), 15.0f), 1e-5f);
    float sB  = fmaxf(div_full(__fsub_rn(mxB, mnB), 15.0f), 1e-5f);

    float qA0f, qA1f, qA2f, qA3f, qB0f, qB1f, qB2f, qB3f;
    float eA0 = quant_deq(dA0, mnA, sA, 15.0f, qA0f);
    float eB0 = quant_deq(dB0, mnB, sB, 15.0f, qB0f);
    float eA1 = quant_deq(dA1, mnA, sA, 15.0f, qA1f);
    float eB1 = quant_deq(dB1, mnB, sB, 15.0f, qB1f);
    float eA2 = quant_deq(dA2, mnA, sA, 15.0f, qA2f);
    float eB2 = quant_deq(dB2, mnB, sB, 15.0f, qB2f);
    float eA3 = quant_deq(dA3, mnA, sA, 15.0f, qA3f);
    float eB3 = quant_deq(dB3, mnB, sB, 15.0f, qB3f);
    int qA0 = (int)qA0f, qA1 = (int)qA1f, qA2 = (int)qA2f, qA3 = (int)qA3f;
    int qB0 = (int)qB0f, qB1 = (int)qB1f, qB2 = (int)qB2f, qB3 = (int)qB3f;

    // ---- Histograms: unpredicated u64 nibble accumulators ----
    unsigned long long hhA = (1ULL << (qA0 << 2)) + (1ULL << (qA1 << 2))
                           + (1ULL << (qA2 << 2)) + (1ULL << (qA3 << 2));
    unsigned long long hhB = (1ULL << (qB0 << 2)) + (1ULL << (qB1 << 2))
                           + (1ULL << (qB2 << 2)) + (1ULL << (qB3 << 2));
    unsigned loA = (unsigned)hhA, hiA = (unsigned)(hhA >> 32);
    unsigned loB = (unsigned)hhB, hiB = (unsigned)(hhB >> 32);
    unsigned hE0A = redux_add_u( loA       & 0x0F0F0F0Fu);
    unsigned hE0B = redux_add_u( loB       & 0x0F0F0F0Fu);
    unsigned hO0A = redux_add_u((loA >> 4) & 0x0F0F0F0Fu);
    unsigned hO0B = redux_add_u((loB >> 4) & 0x0F0F0F0Fu);
    unsigned hE1A = redux_add_u( hiA       & 0x0F0F0F0Fu);
    unsigned hE1B = redux_add_u( hiB       & 0x0F0F0F0Fu);
    unsigned hO1A = redux_add_u((hiA >> 4) & 0x0F0F0F0Fu);
    unsigned hO1B = redux_add_u((hiB >> 4) & 0x0F0F0F0Fu);

    // Mirrored levels: lanes l and l+16 both own level (l & 15).
    int lvl = lane & 15;
    float alvA = fabsf(__fmaf_rn((float)lvl, sA, mnA));
    float alvB = fabsf(__fmaf_rn((float)lvl, sB, mnB));

    // Halved Cle scan, shuffle-free: lanes<16 scan levels [0,8), lanes>=16 [8,16).
    bool hiHalf = (lane & 16) != 0;
    unsigned rEA = hiHalf ? hE1A : hE0A;
    unsigned rOA = hiHalf ? hO1A : hO0A;
    unsigned rEB = hiHalf ? hE1B : hE0B;
    unsigned rOB = hiHalf ? hO1B : hO0B;
    float fbase = hiHalf ? 8.0f : 0.0f;
    int CEA = 0, CEB = 0;
    #pragma unroll
    for (int m = 0; m < 8; m++) {
        float lm  = __fadd_rn(fbase, (float)m);
        float amA = fabsf(__fmaf_rn(lm, sA, mnA));
        float amB = fabsf(__fmaf_rn(lm, sB, mnB));
        unsigned rrA = (m & 1) ? rOA : rEA;
        unsigned rrB = (m & 1) ? rOB : rEB;
        int cmA = __byte_perm(rrA, 0u, 0x4440 | (m >> 1));
        int cmB = __byte_perm(rrB, 0u, 0x4440 | (m >> 1));
        if (amA <= alvA) CEA += cmA;
        if (amB <= alvB) CEB += cmB;
    }
    CEA += __shfl_xor_sync(WFULL, CEA, 16);
    CEB += __shfl_xor_sync(WFULL, CEB, 16);

    // t = min alv among levels with Cle >= 64 (alv >= 0: bits order-isomorphic).
    int keyA = (CEA >= 64) ? __float_as_int(alvA) : 0x7fffffff;
    int keyB = (CEB >= 64) ? __float_as_int(alvB) : 0x7fffffff;
    float tA = __int_as_float(redux_min_i(keyA));
    float tB = __int_as_float(redux_min_i(keyB));
    int CbA = redux_max_i((alvA == tA) ? CEA : 0);
    int CbB = redux_max_i((alvB == tB) ? CEB : 0);

    // Per-element: |e_k| is bit-identical to its level's alv (same FMA).
    int eqA0 = (fabsf(eA0) == tA), eqB0 = (fabsf(eB0) == tB);
    int eqA1 = (fabsf(eA1) == tA), eqB1 = (fabsf(eB1) == tB);
    int eqA2 = (fabsf(eA2) == tA), eqB2 = (fabsf(eB2) == tB);
    int eqA3 = (fabsf(eA3) == tA), eqB3 = (fabsf(eB3) == tB);
    unsigned BA0 = __ballot_sync(WFULL, eqA0), BB0 = __ballot_sync(WFULL, eqB0);
    unsigned BA1 = __ballot_sync(WFULL, eqA1), BB1 = __ballot_sync(WFULL, eqB1);
    unsigned BA2 = __ballot_sync(WFULL, eqA2), BB2 = __ballot_sync(WFULL, eqB2);
    unsigned BA3 = __ballot_sync(WFULL, eqA3), BB3 = __ballot_sync(WFULL, eqB3);
    unsigned below = (1u << lane) - 1u;
    int preA = __popc(BA0 & below) + __popc(BA1 & below)
             + __popc(BA2 & below) + __popc(BA3 & below);
    int preB = __popc(BB0 & below) + __popc(BB1 & below)
             + __popc(BB2 & below) + __popc(BB3 & below);

    int EA = (int)redux_add_u((unsigned)(eqA0 + eqA1 + eqA2 + eqA3));
    int EB = (int)redux_add_u((unsigned)(eqB0 + eqB1 + eqB2 + eqB3));
    int needA = 64 - CbA + EA;
    int needB = 64 - CbB + EB;

    bool zA0 = (fabsf(eA0) < tA) || (eqA0 && (preA                      < needA));
    bool zA1 = (fabsf(eA1) < tA) || (eqA1 && (preA + eqA0               < needA));
    bool zA2 = (fabsf(eA2) < tA) || (eqA2 && (preA + eqA0 + eqA1        < needA));
    bool zA3 = (fabsf(eA3) < tA) || (eqA3 && (preA + eqA0 + eqA1 + eqA2 < needA));
    bool zB0 = (fabsf(eB0) < tB) || (eqB0 && (preB                      < needB));
    bool zB1 = (fabsf(eB1) < tB) || (eqB1 && (preB + eqB0               < needB));
    bool zB2 = (fabsf(eB2) < tB) || (eqB2 && (preB + eqB0 + eqB1        < needB));
    bool zB3 = (fabsf(eB3) < tB) || (eqB3 && (preB + eqB0 + eqB1 + eqB2 < needB));

    float4 oA, oB;
    oA.x = __fadd_rn(bA.x, zA0 ? 0.0f : eA0);
    oA.y = __fadd_rn(bA.y, zA1 ? 0.0f : eA1);
    oA.z = __fadd_rn(bA.z, zA2 ? 0.0f : eA2);
    oA.w = __fadd_rn(bA.w, zA3 ? 0.0f : eA3);
    oB.x = __fadd_rn(bB.x, zB0 ? 0.0f : eB0);
    oB.y = __fadd_rn(bB.y, zB1 ? 0.0f : eB1);
    oB.z = __fadd_rn(bB.z, zB2 ? 0.0f : eB2);
    oB.w = __fadd_rn(bB.w, zB3 ? 0.0f : eB3);
    out4[ia] = oA;
    out4[ib] = oB;
}

extern "C" void kernel_launch(void* const* d_in, const int* in_sizes, int n_in,
                              void* d_out, int out_size) {
    const float* feat = (const float*)d_in[0];
    float* out = (float*)d_out;
    // k1: 8192 warps x 2 base rows = 16384 bases (written into out row-0 slots).
    kvq_base_kernel<<<1024, 256>>>(feat, out);
    // k2: 122880 warps, each = row r of chunk pair (2p, 2p+1), r in 1..15.
    kvq_diff_kernel<<<15360, 256>>>(feat, out);
}